// round 1
// baseline (speedup 1.0000x reference)
#include <cuda_runtime.h>
#include <math.h>
#include <stdint.h>

#define TSEQ 2048
#define BATCH 2
#define CDIM 2048
#define NH 16
#define NKV 4
#define HD 128
#define MROWS (BATCH*TSEQ)          // 4096
#define KVDIM (NKV*HD)              // 512

// ---------------- scratch (no allocation allowed) ----------------
__device__ float g_Q[(size_t)MROWS*CDIM];    // 33.5 MB
__device__ float g_K[(size_t)MROWS*KVDIM];   // 8.4 MB
__device__ float g_V[(size_t)MROWS*KVDIM];   // 8.4 MB
__device__ float g_A[(size_t)MROWS*CDIM];    // 33.5 MB  (attention output, [b*T+t][h*128+d])
__device__ float g_cos[TSEQ*(HD/2)];
__device__ float g_sin[TSEQ*(HD/2)];

// ---------------- RoPE trig table ----------------
// double-precision range reduction so accuracy is independent of fast-math flags
__global__ void fill_trig_kernel() {
    int i = blockIdx.x * blockDim.x + threadIdx.x;
    if (i >= TSEQ * 64) return;
    int t = i >> 6;
    int f = i & 63;
    double theta = exp(((double)(-2 * f) / 128.0) * log(10000.0));
    double ang = (double)t * theta;
    const double twopi = 6.283185307179586476925286766559;
    double k = rint(ang / twopi);
    double r = ang - k * twopi;
    float rf = (float)r;
    g_cos[i] = cosf(rf);
    g_sin[i] = sinf(rf);
}

// ---------------- GEMM: C[M,N] = A[M,K] * B[N,K]^T ----------------
// 128x128 block tile, BK=16, 256 threads, 8x8 per thread (split 4+4 rows/cols
// for conflict-free float4 smem reads).
__global__ __launch_bounds__(256) void gemm_nt_kernel(
    const float* __restrict__ A, const float* __restrict__ B,
    float* __restrict__ C, int M, int N, int K)
{
    __shared__ float As[16][128];
    __shared__ float Bs[16][128];
    const int tid = threadIdx.x;
    const int bm = blockIdx.y * 128;
    const int bn = blockIdx.x * 128;
    const int tx = tid & 15;
    const int ty = tid >> 4;

    float acc[8][8];
#pragma unroll
    for (int i = 0; i < 8; i++)
#pragma unroll
        for (int j = 0; j < 8; j++) acc[i][j] = 0.f;

    for (int k0 = 0; k0 < K; k0 += 16) {
#pragma unroll
        for (int f0 = 0; f0 < 512; f0 += 256) {
            int f = f0 + tid;
            int r = f >> 2;
            int kq = (f & 3) << 2;
            float4 a = *(const float4*)(A + (size_t)(bm + r) * K + k0 + kq);
            As[kq + 0][r] = a.x; As[kq + 1][r] = a.y;
            As[kq + 2][r] = a.z; As[kq + 3][r] = a.w;
            float4 b = *(const float4*)(B + (size_t)(bn + r) * K + k0 + kq);
            Bs[kq + 0][r] = b.x; Bs[kq + 1][r] = b.y;
            Bs[kq + 2][r] = b.z; Bs[kq + 3][r] = b.w;
        }
        __syncthreads();
#pragma unroll
        for (int k = 0; k < 16; k++) {
            float a[8], b[8];
            float4 t0 = *(const float4*)&As[k][ty * 4];
            float4 t1 = *(const float4*)&As[k][64 + ty * 4];
            a[0] = t0.x; a[1] = t0.y; a[2] = t0.z; a[3] = t0.w;
            a[4] = t1.x; a[5] = t1.y; a[6] = t1.z; a[7] = t1.w;
            float4 u0 = *(const float4*)&Bs[k][tx * 4];
            float4 u1 = *(const float4*)&Bs[k][64 + tx * 4];
            b[0] = u0.x; b[1] = u0.y; b[2] = u0.z; b[3] = u0.w;
            b[4] = u1.x; b[5] = u1.y; b[6] = u1.z; b[7] = u1.w;
#pragma unroll
            for (int i = 0; i < 8; i++)
#pragma unroll
                for (int j = 0; j < 8; j++) acc[i][j] += a[i] * b[j];
        }
        __syncthreads();
    }
#pragma unroll
    for (int i = 0; i < 8; i++) {
        int r = bm + ((i >> 2) << 6) + ty * 4 + (i & 3);
        float4 w0 = make_float4(acc[i][0], acc[i][1], acc[i][2], acc[i][3]);
        float4 w1 = make_float4(acc[i][4], acc[i][5], acc[i][6], acc[i][7]);
        *(float4*)(C + (size_t)r * N + bn + tx * 4) = w0;
        *(float4*)(C + (size_t)r * N + bn + 64 + tx * 4) = w1;
    }
}

// ---------------- RMSNorm + RoPE (+ gain & attn scale folded into Q) --------
__global__ __launch_bounds__(128) void norm_rope_kernel(const float* __restrict__ gain) {
    int row = blockIdx.x;
    float* base;
    int t, h;
    bool isQ = row < MROWS * NH;
    if (isQ) {
        int bt = row >> 4; h = row & 15;
        base = g_Q + (size_t)bt * CDIM + h * HD;
        t = bt & (TSEQ - 1);
    } else {
        int r2 = row - MROWS * NH;
        int bt = r2 >> 2; h = r2 & 3;
        base = g_K + (size_t)bt * KVDIM + h * HD;
        t = bt & (TSEQ - 1);
    }
    __shared__ float sh[128];
    __shared__ float red[4];
    int d = threadIdx.x;
    float v = base[d];
    float ss = v * v;
#pragma unroll
    for (int o = 16; o; o >>= 1) ss += __shfl_xor_sync(0xffffffffu, ss, o);
    if ((d & 31) == 0) red[d >> 5] = ss;
    __syncthreads();
    float tot = red[0] + red[1] + red[2] + red[3];
    float inv = rsqrtf(tot * (1.0f / 128.0f) + 1.1920928955078125e-07f);
    sh[d] = v * inv;
    __syncthreads();
    if (d < 64) {
        float te = sh[2 * d], to = sh[2 * d + 1];
        float c = g_cos[t * 64 + d];
        float s = g_sin[t * 64 + d];
        float re = te * c - to * s;
        float ro = te * s + to * c;
        float g = isQ ? gain[h] * 0.08838834764831845f : 1.0f;  // gain * 1/sqrt(128)
        base[2 * d] = re * g;
        base[2 * d + 1] = ro * g;
    }
}

// ---------------- Flash attention (fp32, causal, GQA) ----------------
// 64 q-rows x 64 k-cols per tile, 256 threads (16x16), each thread: 4 q-rows,
// 4 s-cols (split 2+2), 8 o-cols (split 4+4). smem: Q^T, K^T [128][68], V
// [64][128], P [64][68]. ~117 KB dynamic smem -> 1 CTA/SM.
#define ATTN_SMEM_FLOATS (128*68 + 128*68 + 64*128 + 64*68)
__global__ __launch_bounds__(256) void attn_kernel() {
    extern __shared__ float sm[];
    float* Qt = sm;               // [128][68] transposed
    float* Kt = Qt + 128 * 68;    // [128][68] transposed
    float* Vs = Kt + 128 * 68;    // [64][128]
    float* Ps = Vs + 64 * 128;    // [64][68]
    const int qt = blockIdx.x, h = blockIdx.y, b = blockIdx.z;
    const int kvh = h >> 2;
    const float* Qb = g_Q + (size_t)b * TSEQ * CDIM + h * HD;
    const float* Kb = g_K + (size_t)b * TSEQ * KVDIM + kvh * HD;
    const float* Vb = g_V + (size_t)b * TSEQ * KVDIM + kvh * HD;
    float* Ob = g_A + (size_t)b * TSEQ * CDIM + h * HD;
    const int tid = threadIdx.x;
    const int tx = tid & 15, ty = tid >> 4;
    const int q0 = qt * 64;

    // load Q tile transposed
    for (int f = tid; f < 2048; f += 256) {
        int r = f >> 5;
        int d4 = (f & 31) << 2;
        float4 v = *(const float4*)(Qb + (size_t)(q0 + r) * CDIM + d4);
        Qt[(d4 + 0) * 68 + r] = v.x;
        Qt[(d4 + 1) * 68 + r] = v.y;
        Qt[(d4 + 2) * 68 + r] = v.z;
        Qt[(d4 + 3) * 68 + r] = v.w;
    }

    float m[4] = {-1e30f, -1e30f, -1e30f, -1e30f};
    float l[4] = {0.f, 0.f, 0.f, 0.f};
    float o[4][8];
#pragma unroll
    for (int i = 0; i < 4; i++)
#pragma unroll
        for (int j = 0; j < 8; j++) o[i][j] = 0.f;

    for (int kt = 0; kt <= qt; kt++) {
        const int k0 = kt * 64;
        __syncthreads();  // previous P@V done; Q load done (first iter)
        for (int f = tid; f < 2048; f += 256) {
            int r = f >> 5;
            int d4 = (f & 31) << 2;
            float4 v = *(const float4*)(Kb + (size_t)(k0 + r) * KVDIM + d4);
            Kt[(d4 + 0) * 68 + r] = v.x;
            Kt[(d4 + 1) * 68 + r] = v.y;
            Kt[(d4 + 2) * 68 + r] = v.z;
            Kt[(d4 + 3) * 68 + r] = v.w;
            float4 w = *(const float4*)(Vb + (size_t)(k0 + r) * KVDIM + d4);
            *(float4*)(Vs + r * 128 + d4) = w;
        }
        __syncthreads();

        // ---- S = Q K^T (scale prefolded into Q) ----
        float s[4][4];
#pragma unroll
        for (int i = 0; i < 4; i++)
#pragma unroll
            for (int j = 0; j < 4; j++) s[i][j] = 0.f;
#pragma unroll 4
        for (int d = 0; d < 128; d++) {
            float a0 = Qt[d * 68 + ty * 4 + 0];
            float a1 = Qt[d * 68 + ty * 4 + 1];
            float a2 = Qt[d * 68 + ty * 4 + 2];
            float a3 = Qt[d * 68 + ty * 4 + 3];
            float b0 = Kt[d * 68 + tx * 2 + 0];
            float b1 = Kt[d * 68 + tx * 2 + 1];
            float b2 = Kt[d * 68 + 32 + tx * 2 + 0];
            float b3 = Kt[d * 68 + 32 + tx * 2 + 1];
            s[0][0] += a0 * b0; s[0][1] += a0 * b1; s[0][2] += a0 * b2; s[0][3] += a0 * b3;
            s[1][0] += a1 * b0; s[1][1] += a1 * b1; s[1][2] += a1 * b2; s[1][3] += a1 * b3;
            s[2][0] += a2 * b0; s[2][1] += a2 * b1; s[2][2] += a2 * b2; s[2][3] += a2 * b3;
            s[3][0] += a3 * b0; s[3][1] += a3 * b1; s[3][2] += a3 * b2; s[3][3] += a3 * b3;
        }

        // ---- causal mask (diag tile only) ----
        if (kt == qt) {
#pragma unroll
            for (int i = 0; i < 4; i++) {
                int qr = q0 + ty * 4 + i;
#pragma unroll
                for (int j = 0; j < 4; j++) {
                    int kc = k0 + ((j >> 1) << 5) + tx * 2 + (j & 1);
                    if (kc > qr) s[i][j] = -1e30f;
                }
            }
        }

        // ---- online softmax ----
        float p[4][4];
#pragma unroll
        for (int i = 0; i < 4; i++) {
            float rm = fmaxf(fmaxf(s[i][0], s[i][1]), fmaxf(s[i][2], s[i][3]));
#pragma unroll
            for (int off = 8; off >= 1; off >>= 1)
                rm = fmaxf(rm, __shfl_xor_sync(0xffffffffu, rm, off));
            float mn = fmaxf(m[i], rm);
            float corr = __expf(m[i] - mn);
            p[i][0] = __expf(s[i][0] - mn);
            p[i][1] = __expf(s[i][1] - mn);
            p[i][2] = __expf(s[i][2] - mn);
            p[i][3] = __expf(s[i][3] - mn);
            float su = p[i][0] + p[i][1] + p[i][2] + p[i][3];
#pragma unroll
            for (int off = 8; off >= 1; off >>= 1)
                su += __shfl_xor_sync(0xffffffffu, su, off);
            l[i] = l[i] * corr + su;
            m[i] = mn;
#pragma unroll
            for (int j = 0; j < 8; j++) o[i][j] *= corr;
        }

        // ---- share P ----
#pragma unroll
        for (int i = 0; i < 4; i++) {
#pragma unroll
            for (int j = 0; j < 4; j++)
                Ps[(ty * 4 + i) * 68 + ((j >> 1) << 5) + tx * 2 + (j & 1)] = p[i][j];
        }
        __syncthreads();

        // ---- O += P V ----
#pragma unroll 4
        for (int kk = 0; kk < 64; kk++) {
            float a0 = Ps[(ty * 4 + 0) * 68 + kk];
            float a1 = Ps[(ty * 4 + 1) * 68 + kk];
            float a2 = Ps[(ty * 4 + 2) * 68 + kk];
            float a3 = Ps[(ty * 4 + 3) * 68 + kk];
            float4 v0 = *(const float4*)(Vs + kk * 128 + tx * 4);
            float4 v1 = *(const float4*)(Vs + kk * 128 + 64 + tx * 4);
            o[0][0] += a0 * v0.x; o[0][1] += a0 * v0.y; o[0][2] += a0 * v0.z; o[0][3] += a0 * v0.w;
            o[0][4] += a0 * v1.x; o[0][5] += a0 * v1.y; o[0][6] += a0 * v1.z; o[0][7] += a0 * v1.w;
            o[1][0] += a1 * v0.x; o[1][1] += a1 * v0.y; o[1][2] += a1 * v0.z; o[1][3] += a1 * v0.w;
            o[1][4] += a1 * v1.x; o[1][5] += a1 * v1.y; o[1][6] += a1 * v1.z; o[1][7] += a1 * v1.w;
            o[2][0] += a2 * v0.x; o[2][1] += a2 * v0.y; o[2][2] += a2 * v0.z; o[2][3] += a2 * v0.w;
            o[2][4] += a2 * v1.x; o[2][5] += a2 * v1.y; o[2][6] += a2 * v1.z; o[2][7] += a2 * v1.w;
            o[3][0] += a3 * v0.x; o[3][1] += a3 * v0.y; o[3][2] += a3 * v0.z; o[3][3] += a3 * v0.w;
            o[3][4] += a3 * v1.x; o[3][5] += a3 * v1.y; o[3][6] += a3 * v1.z; o[3][7] += a3 * v1.w;
        }
    }

    // ---- epilogue: normalize + store ----
#pragma unroll
    for (int i = 0; i < 4; i++) {
        float inv = 1.0f / l[i];
        int r = q0 + ty * 4 + i;
        float4 w0 = make_float4(o[i][0] * inv, o[i][1] * inv, o[i][2] * inv, o[i][3] * inv);
        float4 w1 = make_float4(o[i][4] * inv, o[i][5] * inv, o[i][6] * inv, o[i][7] * inv);
        *(float4*)(Ob + (size_t)r * CDIM + tx * 4) = w0;
        *(float4*)(Ob + (size_t)r * CDIM + 64 + tx * 4) = w1;
    }
}

// ---------------- launch ----------------
extern "C" void kernel_launch(void* const* d_in, const int* in_sizes, int n_in,
                              void* d_out, int out_size) {
    const float* x    = (const float*)d_in[0];
    const float* Wq   = (const float*)d_in[1];
    const float* Wk   = (const float*)d_in[2];
    const float* Wv   = (const float*)d_in[3];
    const float* Wo   = (const float*)d_in[4];
    const float* gain = (const float*)d_in[5];
    float* out = (float*)d_out;

    float *pQ, *pK, *pV, *pA;
    cudaGetSymbolAddress((void**)&pQ, g_Q);
    cudaGetSymbolAddress((void**)&pK, g_K);
    cudaGetSymbolAddress((void**)&pV, g_V);
    cudaGetSymbolAddress((void**)&pA, g_A);

    cudaFuncSetAttribute(attn_kernel, cudaFuncAttributeMaxDynamicSharedMemorySize,
                         ATTN_SMEM_FLOATS * (int)sizeof(float));

    fill_trig_kernel<<<(TSEQ * 64 + 255) / 256, 256>>>();

    dim3 gq(CDIM / 128, MROWS / 128);     // (16, 32)
    gemm_nt_kernel<<<gq, 256>>>(x, Wq, pQ, MROWS, CDIM, CDIM);
    dim3 gkv(KVDIM / 128, MROWS / 128);   // (4, 32)
    gemm_nt_kernel<<<gkv, 256>>>(x, Wk, pK, MROWS, KVDIM, CDIM);
    gemm_nt_kernel<<<gkv, 256>>>(x, Wv, pV, MROWS, KVDIM, CDIM);

    norm_rope_kernel<<<MROWS * NH + MROWS * NKV, 128>>>(gain);

    dim3 ga(TSEQ / 64, NH, BATCH);
    attn_kernel<<<ga, 256, ATTN_SMEM_FLOATS * (int)sizeof(float)>>>();

    gemm_nt_kernel<<<gq, 256>>>(pA, Wo, out, MROWS, CDIM, CDIM);
}

// round 4
// speedup vs baseline: 1.5436x; 1.5436x over previous
#include <cuda_runtime.h>
#include <cuda_bf16.h>
#include <math.h>
#include <stdint.h>

#define TSEQ 2048
#define BATCH 2
#define CDIM 2048
#define NH 16
#define NKV 4
#define HD 128
#define MROWS (BATCH*TSEQ)          // 4096
#define KVDIM (NKV*HD)              // 512

// ---------------- scratch (no allocation allowed) ----------------
__device__ float g_Q[(size_t)MROWS*CDIM];
__device__ float g_K[(size_t)MROWS*KVDIM];
__device__ float g_V[(size_t)MROWS*KVDIM];
__device__ float g_A[(size_t)MROWS*CDIM];
__device__ float g_cos[TSEQ*(HD/2)];
__device__ float g_sin[TSEQ*(HD/2)];

// bf16 hi/lo split buffers
__device__ __nv_bfloat16 g_xh[(size_t)MROWS*CDIM];
__device__ __nv_bfloat16 g_xl[(size_t)MROWS*CDIM];
__device__ __nv_bfloat16 g_Wqh[(size_t)CDIM*CDIM];
__device__ __nv_bfloat16 g_Wql[(size_t)CDIM*CDIM];
__device__ __nv_bfloat16 g_Wkh[(size_t)KVDIM*CDIM];
__device__ __nv_bfloat16 g_Wkl[(size_t)KVDIM*CDIM];
__device__ __nv_bfloat16 g_Wvh[(size_t)KVDIM*CDIM];
__device__ __nv_bfloat16 g_Wvl[(size_t)KVDIM*CDIM];
__device__ __nv_bfloat16 g_Woh[(size_t)CDIM*CDIM];
__device__ __nv_bfloat16 g_Wol[(size_t)CDIM*CDIM];
__device__ __nv_bfloat16 g_Ahh[(size_t)MROWS*CDIM];
__device__ __nv_bfloat16 g_All[(size_t)MROWS*CDIM];

// ---------------- small helpers ----------------
__device__ __forceinline__ uint32_t smem_u32(const void* p){
    uint32_t a;
    asm("{ .reg .u64 t; cvta.to.shared.u64 t, %1; cvt.u32.u64 %0, t; }" : "=r"(a) : "l"(p));
    return a;
}
__device__ __forceinline__ void cp16(uint32_t dst, const void* src){
    asm volatile("cp.async.cg.shared.global [%0], [%1], 16;" :: "r"(dst), "l"(src) : "memory");
}
#define CP_COMMIT() asm volatile("cp.async.commit_group;" ::: "memory")
#define CP_WAIT1()  asm volatile("cp.async.wait_group 1;" ::: "memory")

__device__ __forceinline__ void mma_bf16(float* c, const uint32_t* a, uint32_t b0, uint32_t b1){
    asm volatile(
        "mma.sync.aligned.m16n8k16.row.col.f32.bf16.bf16.f32 "
        "{%0,%1,%2,%3}, {%4,%5,%6,%7}, {%8,%9}, {%0,%1,%2,%3};"
        : "+f"(c[0]), "+f"(c[1]), "+f"(c[2]), "+f"(c[3])
        : "r"(a[0]), "r"(a[1]), "r"(a[2]), "r"(a[3]), "r"(b0), "r"(b1));
}
__device__ __forceinline__ uint32_t ld2bf(const __nv_bfloat16* p){
    return *(const uint32_t*)p;
}

// ---------------- RoPE trig table ----------------
__global__ void fill_trig_kernel() {
    int i = blockIdx.x * blockDim.x + threadIdx.x;
    if (i >= TSEQ * 64) return;
    int t = i >> 6;
    int f = i & 63;
    double theta = exp(((double)(-2 * f) / 128.0) * log(10000.0));
    double ang = (double)t * theta;
    const double twopi = 6.283185307179586476925286766559;
    double k = rint(ang / twopi);
    float rf = (float)(ang - k * twopi);
    g_cos[i] = cosf(rf);
    g_sin[i] = sinf(rf);
}

// ---------------- fp32 -> bf16 hi/lo split ----------------
__global__ __launch_bounds__(256) void split_kernel(
    const float* __restrict__ in, __nv_bfloat16* __restrict__ hi,
    __nv_bfloat16* __restrict__ lo, int n4)
{
    int i = blockIdx.x * blockDim.x + threadIdx.x;
    if (i >= n4) return;
    float4 v = ((const float4*)in)[i];
    __nv_bfloat16 h0 = __float2bfloat16(v.x);
    __nv_bfloat16 h1 = __float2bfloat16(v.y);
    __nv_bfloat16 h2 = __float2bfloat16(v.z);
    __nv_bfloat16 h3 = __float2bfloat16(v.w);
    __nv_bfloat16 l0 = __float2bfloat16(v.x - __bfloat162float(h0));
    __nv_bfloat16 l1 = __float2bfloat16(v.y - __bfloat162float(h1));
    __nv_bfloat16 l2 = __float2bfloat16(v.z - __bfloat162float(h2));
    __nv_bfloat16 l3 = __float2bfloat16(v.w - __bfloat162float(h3));
    ((__nv_bfloat162*)hi)[2*i+0] = __nv_bfloat162(h0, h1);
    ((__nv_bfloat162*)hi)[2*i+1] = __nv_bfloat162(h2, h3);
    ((__nv_bfloat162*)lo)[2*i+0] = __nv_bfloat162(l0, l1);
    ((__nv_bfloat162*)lo)[2*i+1] = __nv_bfloat162(l2, l3);
}

// ------- bf16 split tensor-core GEMM: C[M,N] = A[M,K] * B[N,K]^T -----------
// C = Ah*Bh + Ah*Bl + Al*Bh  (fp32 accum).  128x128 CTA tile, 8 warps (4x2),
// warp tile 32x64, BK=32, cp.async 2-stage pipeline.
#define BPAD 40                        // bf16 row stride (conflict-free)
#define TEL (128*BPAD)                 // elems per tensor tile (5120)
#define STAGE_EL (4*TEL)               // Ah, Al, Bh, Bl
#define GEMM_SMEM_BYTES (2*STAGE_EL*2) // 81920

__global__ __launch_bounds__(256, 2) void bf16_gemm_kernel(
    const __nv_bfloat16* __restrict__ Ahp, const __nv_bfloat16* __restrict__ Alp,
    const __nv_bfloat16* __restrict__ Bhp, const __nv_bfloat16* __restrict__ Blp,
    float* __restrict__ C, int M, int N, int K)
{
    extern __shared__ __nv_bfloat16 smbf[];
    const int tid = threadIdx.x;
    const int wid = tid >> 5, lane = tid & 31;
    const int g = lane >> 2, t4 = lane & 3;
    const int wm = (wid >> 1) * 32;
    const int wn = (wid & 1) * 64;
    const int bm = blockIdx.y * 128, bn = blockIdx.x * 128;

    const uint32_t smb = smem_u32(smbf);
    // loader mapping: idx -> row (0..127), 16B chunk (0..3)
    const int lr = tid >> 1;               // rows 0..127 (passes cover halves)
    // we use: idx = tid + p*256; r = idx>>2; c8 = (idx&3)*8
    float acc[2][8][4];
#pragma unroll
    for (int i = 0; i < 2; i++)
#pragma unroll
        for (int j = 0; j < 8; j++)
#pragma unroll
            for (int q = 0; q < 4; q++) acc[i][j][q] = 0.f;
    (void)lr;

    const int nch = K / 32;

    auto issue_chunk = [&](int c, int st) {
        const int k0 = c * 32;
        const uint32_t so = (uint32_t)st * (STAGE_EL * 2);
        const __nv_bfloat16* srcs[4] = {
            Ahp + (size_t)bm * K + k0, Alp + (size_t)bm * K + k0,
            Bhp + (size_t)bn * K + k0, Blp + (size_t)bn * K + k0 };
#pragma unroll
        for (int t = 0; t < 4; t++) {
#pragma unroll
            for (int p = 0; p < 2; p++) {
                int idx = tid + p * 256;
                int r = idx >> 2;
                int c8 = (idx & 3) * 8;
                cp16(smb + so + (uint32_t)(t * TEL + r * BPAD + c8) * 2u,
                     srcs[t] + (size_t)r * K + c8);
            }
        }
    };

    issue_chunk(0, 0); CP_COMMIT();
    issue_chunk(1, 1); CP_COMMIT();

    for (int c = 0; c < nch; c++) {
        CP_WAIT1();
        __syncthreads();
        const int st = c & 1;
        const __nv_bfloat16* Ahs = smbf + st * STAGE_EL;
        const __nv_bfloat16* Als = Ahs + TEL;
        const __nv_bfloat16* Bhs = Als + TEL;
        const __nv_bfloat16* Bls = Bhs + TEL;

#pragma unroll
        for (int kk = 0; kk < 32; kk += 16) {
            uint32_t ah[2][4], al[2][4];
#pragma unroll
            for (int mt = 0; mt < 2; mt++) {
                const __nv_bfloat16* ap = Ahs + (wm + mt * 16 + g) * BPAD + kk + 2 * t4;
                ah[mt][0] = ld2bf(ap);
                ah[mt][1] = ld2bf(ap + 8 * BPAD);
                ah[mt][2] = ld2bf(ap + 8);
                ah[mt][3] = ld2bf(ap + 8 * BPAD + 8);
                const __nv_bfloat16* aq = Als + (wm + mt * 16 + g) * BPAD + kk + 2 * t4;
                al[mt][0] = ld2bf(aq);
                al[mt][1] = ld2bf(aq + 8 * BPAD);
                al[mt][2] = ld2bf(aq + 8);
                al[mt][3] = ld2bf(aq + 8 * BPAD + 8);
            }
#pragma unroll
            for (int nt = 0; nt < 8; nt++) {
                const __nv_bfloat16* bp = Bhs + (wn + nt * 8 + g) * BPAD + kk + 2 * t4;
                uint32_t b0h = ld2bf(bp);
                uint32_t b1h = ld2bf(bp + 8);
                const __nv_bfloat16* bq = Bls + (wn + nt * 8 + g) * BPAD + kk + 2 * t4;
                uint32_t b0l = ld2bf(bq);
                uint32_t b1l = ld2bf(bq + 8);
                mma_bf16(acc[0][nt], ah[0], b0h, b1h);
                mma_bf16(acc[1][nt], ah[1], b0h, b1h);
                mma_bf16(acc[0][nt], ah[0], b0l, b1l);
                mma_bf16(acc[1][nt], ah[1], b0l, b1l);
                mma_bf16(acc[0][nt], al[0], b0h, b1h);
                mma_bf16(acc[1][nt], al[1], b0h, b1h);
            }
        }
        __syncthreads();
        if (c + 2 < nch) issue_chunk(c + 2, st);
        CP_COMMIT();
    }

    // epilogue
#pragma unroll
    for (int mt = 0; mt < 2; mt++) {
        int r0 = bm + wm + mt * 16 + g;
#pragma unroll
        for (int nt = 0; nt < 8; nt++) {
            int col = bn + wn + nt * 8 + 2 * t4;
            float2 w0 = make_float2(acc[mt][nt][0], acc[mt][nt][1]);
            float2 w1 = make_float2(acc[mt][nt][2], acc[mt][nt][3]);
            *(float2*)(C + (size_t)r0 * N + col) = w0;
            *(float2*)(C + (size_t)(r0 + 8) * N + col) = w1;
        }
    }
}

// ---------------- RMSNorm + RoPE (+ gain & attn scale folded into Q) --------
__global__ __launch_bounds__(128) void norm_rope_kernel(const float* __restrict__ gain) {
    int row = blockIdx.x;
    float* base;
    int t, h;
    bool isQ = row < MROWS * NH;
    if (isQ) {
        int bt = row >> 4; h = row & 15;
        base = g_Q + (size_t)bt * CDIM + h * HD;
        t = bt & (TSEQ - 1);
    } else {
        int r2 = row - MROWS * NH;
        int bt = r2 >> 2; h = r2 & 3;
        base = g_K + (size_t)bt * KVDIM + h * HD;
        t = bt & (TSEQ - 1);
    }
    __shared__ float sh[128];
    __shared__ float red[4];
    int d = threadIdx.x;
    float v = base[d];
    float ss = v * v;
#pragma unroll
    for (int o = 16; o; o >>= 1) ss += __shfl_xor_sync(0xffffffffu, ss, o);
    if ((d & 31) == 0) red[d >> 5] = ss;
    __syncthreads();
    float tot = red[0] + red[1] + red[2] + red[3];
    float inv = rsqrtf(tot * (1.0f / 128.0f) + 1.1920928955078125e-07f);
    sh[d] = v * inv;
    __syncthreads();
    if (d < 64) {
        float te = sh[2 * d], to = sh[2 * d + 1];
        float c = g_cos[t * 64 + d];
        float s = g_sin[t * 64 + d];
        float re = te * c - to * s;
        float ro = te * s + to * c;
        float g = isQ ? gain[h] * 0.08838834764831845f : 1.0f;
        base[2 * d] = re * g;
        base[2 * d + 1] = ro * g;
    }
}

// ---------------- Flash attention (fp32, causal, GQA) ----------------
#define ATTN_SMEM_FLOATS (128*68 + 128*68 + 64*128 + 64*68)
__global__ __launch_bounds__(256) void attn_kernel() {
    extern __shared__ float sm[];
    float* Qt = sm;
    float* Kt = Qt + 128 * 68;
    float* Vs = Kt + 128 * 68;
    float* Ps = Vs + 64 * 128;
    const int qt = blockIdx.x, h = blockIdx.y, b = blockIdx.z;
    const int kvh = h >> 2;
    const float* Qb = g_Q + (size_t)b * TSEQ * CDIM + h * HD;
    const float* Kb = g_K + (size_t)b * TSEQ * KVDIM + kvh * HD;
    const float* Vb = g_V + (size_t)b * TSEQ * KVDIM + kvh * HD;
    float* Ob = g_A + (size_t)b * TSEQ * CDIM + h * HD;
    const int tid = threadIdx.x;
    const int tx = tid & 15, ty = tid >> 4;
    const int q0 = qt * 64;

    for (int f = tid; f < 2048; f += 256) {
        int r = f >> 5;
        int d4 = (f & 31) << 2;
        float4 v = *(const float4*)(Qb + (size_t)(q0 + r) * CDIM + d4);
        Qt[(d4 + 0) * 68 + r] = v.x;
        Qt[(d4 + 1) * 68 + r] = v.y;
        Qt[(d4 + 2) * 68 + r] = v.z;
        Qt[(d4 + 3) * 68 + r] = v.w;
    }

    float m[4] = {-1e30f, -1e30f, -1e30f, -1e30f};
    float l[4] = {0.f, 0.f, 0.f, 0.f};
    float o[4][8];
#pragma unroll
    for (int i = 0; i < 4; i++)
#pragma unroll
        for (int j = 0; j < 8; j++) o[i][j] = 0.f;

    for (int kt = 0; kt <= qt; kt++) {
        const int k0 = kt * 64;
        __syncthreads();
        for (int f = tid; f < 2048; f += 256) {
            int r = f >> 5;
            int d4 = (f & 31) << 2;
            float4 v = *(const float4*)(Kb + (size_t)(k0 + r) * KVDIM + d4);
            Kt[(d4 + 0) * 68 + r] = v.x;
            Kt[(d4 + 1) * 68 + r] = v.y;
            Kt[(d4 + 2) * 68 + r] = v.z;
            Kt[(d4 + 3) * 68 + r] = v.w;
            float4 w = *(const float4*)(Vb + (size_t)(k0 + r) * KVDIM + d4);
            *(float4*)(Vs + r * 128 + d4) = w;
        }
        __syncthreads();

        float s[4][4];
#pragma unroll
        for (int i = 0; i < 4; i++)
#pragma unroll
            for (int j = 0; j < 4; j++) s[i][j] = 0.f;
#pragma unroll 4
        for (int d = 0; d < 128; d++) {
            float a0 = Qt[d * 68 + ty * 4 + 0];
            float a1 = Qt[d * 68 + ty * 4 + 1];
            float a2 = Qt[d * 68 + ty * 4 + 2];
            float a3 = Qt[d * 68 + ty * 4 + 3];
            float b0 = Kt[d * 68 + tx * 2 + 0];
            float b1 = Kt[d * 68 + tx * 2 + 1];
            float b2 = Kt[d * 68 + 32 + tx * 2 + 0];
            float b3 = Kt[d * 68 + 32 + tx * 2 + 1];
            s[0][0] += a0 * b0; s[0][1] += a0 * b1; s[0][2] += a0 * b2; s[0][3] += a0 * b3;
            s[1][0] += a1 * b0; s[1][1] += a1 * b1; s[1][2] += a1 * b2; s[1][3] += a1 * b3;
            s[2][0] += a2 * b0; s[2][1] += a2 * b1; s[2][2] += a2 * b2; s[2][3] += a2 * b3;
            s[3][0] += a3 * b0; s[3][1] += a3 * b1; s[3][2] += a3 * b2; s[3][3] += a3 * b3;
        }

        if (kt == qt) {
#pragma unroll
            for (int i = 0; i < 4; i++) {
                int qr = q0 + ty * 4 + i;
#pragma unroll
                for (int j = 0; j < 4; j++) {
                    int kc = k0 + ((j >> 1) << 5) + tx * 2 + (j & 1);
                    if (kc > qr) s[i][j] = -1e30f;
                }
            }
        }

        float p[4][4];
#pragma unroll
        for (int i = 0; i < 4; i++) {
            float rm = fmaxf(fmaxf(s[i][0], s[i][1]), fmaxf(s[i][2], s[i][3]));
#pragma unroll
            for (int off = 8; off >= 1; off >>= 1)
                rm = fmaxf(rm, __shfl_xor_sync(0xffffffffu, rm, off));
            float mn = fmaxf(m[i], rm);
            float corr = __expf(m[i] - mn);
            p[i][0] = __expf(s[i][0] - mn);
            p[i][1] = __expf(s[i][1] - mn);
            p[i][2] = __expf(s[i][2] - mn);
            p[i][3] = __expf(s[i][3] - mn);
            float su = p[i][0] + p[i][1] + p[i][2] + p[i][3];
#pragma unroll
            for (int off = 8; off >= 1; off >>= 1)
                su += __shfl_xor_sync(0xffffffffu, su, off);
            l[i] = l[i] * corr + su;
            m[i] = mn;
#pragma unroll
            for (int j = 0; j < 8; j++) o[i][j] *= corr;
        }

#pragma unroll
        for (int i = 0; i < 4; i++) {
#pragma unroll
            for (int j = 0; j < 4; j++)
                Ps[(ty * 4 + i) * 68 + ((j >> 1) << 5) + tx * 2 + (j & 1)] = p[i][j];
        }
        __syncthreads();

#pragma unroll 4
        for (int kk = 0; kk < 64; kk++) {
            float a0 = Ps[(ty * 4 + 0) * 68 + kk];
            float a1 = Ps[(ty * 4 + 1) * 68 + kk];
            float a2 = Ps[(ty * 4 + 2) * 68 + kk];
            float a3 = Ps[(ty * 4 + 3) * 68 + kk];
            float4 v0 = *(const float4*)(Vs + kk * 128 + tx * 4);
            float4 v1 = *(const float4*)(Vs + kk * 128 + 64 + tx * 4);
            o[0][0] += a0 * v0.x; o[0][1] += a0 * v0.y; o[0][2] += a0 * v0.z; o[0][3] += a0 * v0.w;
            o[0][4] += a0 * v1.x; o[0][5] += a0 * v1.y; o[0][6] += a0 * v1.z; o[0][7] += a0 * v1.w;
            o[1][0] += a1 * v0.x; o[1][1] += a1 * v0.y; o[1][2] += a1 * v0.z; o[1][3] += a1 * v0.w;
            o[1][4] += a1 * v1.x; o[1][5] += a1 * v1.y; o[1][6] += a1 * v1.z; o[1][7] += a1 * v1.w;
            o[2][0] += a2 * v0.x; o[2][1] += a2 * v0.y; o[2][2] += a2 * v0.z; o[2][3] += a2 * v0.w;
            o[2][4] += a2 * v1.x; o[2][5] += a2 * v1.y; o[2][6] += a2 * v1.z; o[2][7] += a2 * v1.w;
            o[3][0] += a3 * v0.x; o[3][1] += a3 * v0.y; o[3][2] += a3 * v0.z; o[3][3] += a3 * v0.w;
            o[3][4] += a3 * v1.x; o[3][5] += a3 * v1.y; o[3][6] += a3 * v1.z; o[3][7] += a3 * v1.w;
        }
    }

#pragma unroll
    for (int i = 0; i < 4; i++) {
        float inv = 1.0f / l[i];
        int r = q0 + ty * 4 + i;
        float4 w0 = make_float4(o[i][0] * inv, o[i][1] * inv, o[i][2] * inv, o[i][3] * inv);
        float4 w1 = make_float4(o[i][4] * inv, o[i][5] * inv, o[i][6] * inv, o[i][7] * inv);
        *(float4*)(Ob + (size_t)r * CDIM + tx * 4) = w0;
        *(float4*)(Ob + (size_t)r * CDIM + 64 + tx * 4) = w1;
    }
}

// ---------------- launch ----------------
extern "C" void kernel_launch(void* const* d_in, const int* in_sizes, int n_in,
                              void* d_out, int out_size) {
    const float* x    = (const float*)d_in[0];
    const float* Wq   = (const float*)d_in[1];
    const float* Wk   = (const float*)d_in[2];
    const float* Wv   = (const float*)d_in[3];
    const float* Wo   = (const float*)d_in[4];
    const float* gain = (const float*)d_in[5];
    float* out = (float*)d_out;

    float *pQ, *pK, *pV, *pA;
    cudaGetSymbolAddress((void**)&pQ, g_Q);
    cudaGetSymbolAddress((void**)&pK, g_K);
    cudaGetSymbolAddress((void**)&pV, g_V);
    cudaGetSymbolAddress((void**)&pA, g_A);
    __nv_bfloat16 *xh, *xl, *wqh, *wql, *wkh, *wkl, *wvh, *wvl, *woh, *wol, *ah, *al;
    cudaGetSymbolAddress((void**)&xh, g_xh);   cudaGetSymbolAddress((void**)&xl, g_xl);
    cudaGetSymbolAddress((void**)&wqh, g_Wqh); cudaGetSymbolAddress((void**)&wql, g_Wql);
    cudaGetSymbolAddress((void**)&wkh, g_Wkh); cudaGetSymbolAddress((void**)&wkl, g_Wkl);
    cudaGetSymbolAddress((void**)&wvh, g_Wvh); cudaGetSymbolAddress((void**)&wvl, g_Wvl);
    cudaGetSymbolAddress((void**)&woh, g_Woh); cudaGetSymbolAddress((void**)&wol, g_Wol);
    cudaGetSymbolAddress((void**)&ah, g_Ahh);  cudaGetSymbolAddress((void**)&al, g_All);

    cudaFuncSetAttribute(attn_kernel, cudaFuncAttributeMaxDynamicSharedMemorySize,
                         ATTN_SMEM_FLOATS * (int)sizeof(float));
    cudaFuncSetAttribute(bf16_gemm_kernel, cudaFuncAttributeMaxDynamicSharedMemorySize,
                         GEMM_SMEM_BYTES);

    fill_trig_kernel<<<(TSEQ * 64 + 255) / 256, 256>>>();

    // splits
    split_kernel<<<(MROWS*CDIM/4 + 255)/256, 256>>>(x, xh, xl, MROWS*CDIM/4);
    split_kernel<<<(CDIM*CDIM/4 + 255)/256, 256>>>(Wq, wqh, wql, CDIM*CDIM/4);
    split_kernel<<<(KVDIM*CDIM/4 + 255)/256, 256>>>(Wk, wkh, wkl, KVDIM*CDIM/4);
    split_kernel<<<(KVDIM*CDIM/4 + 255)/256, 256>>>(Wv, wvh, wvl, KVDIM*CDIM/4);
    split_kernel<<<(CDIM*CDIM/4 + 255)/256, 256>>>(Wo, woh, wol, CDIM*CDIM/4);

    // projections (tensor cores, 3-term bf16 split)
    dim3 gq(CDIM / 128, MROWS / 128);     // (16, 32)
    dim3 gkv(KVDIM / 128, MROWS / 128);   // (4, 32)
    bf16_gemm_kernel<<<gq,  256, GEMM_SMEM_BYTES>>>(xh, xl, wqh, wql, pQ, MROWS, CDIM, CDIM);
    bf16_gemm_kernel<<<gkv, 256, GEMM_SMEM_BYTES>>>(xh, xl, wkh, wkl, pK, MROWS, KVDIM, CDIM);
    bf16_gemm_kernel<<<gkv, 256, GEMM_SMEM_BYTES>>>(xh, xl, wvh, wvl, pV, MROWS, KVDIM, CDIM);

    norm_rope_kernel<<<MROWS * NH + MROWS * NKV, 128>>>(gain);

    dim3 ga(TSEQ / 64, NH, BATCH);
    attn_kernel<<<ga, 256, ATTN_SMEM_FLOATS * (int)sizeof(float)>>>();

    // O projection
    split_kernel<<<(MROWS*CDIM/4 + 255)/256, 256>>>(pA, ah, al, MROWS*CDIM/4);
    bf16_gemm_kernel<<<gq, 256, GEMM_SMEM_BYTES>>>(ah, al, woh, wol, out, MROWS, CDIM, CDIM);
}

// round 5
// speedup vs baseline: 2.4903x; 1.6133x over previous
#include <cuda_runtime.h>
#include <cuda_bf16.h>
#include <math.h>
#include <stdint.h>

#define TSEQ 2048
#define BATCH 2
#define CDIM 2048
#define NH 16
#define NKV 4
#define HD 128
#define MROWS (BATCH*TSEQ)          // 4096
#define KVDIM (NKV*HD)              // 512

// ---------------- scratch (no allocation allowed) ----------------
__device__ float g_Q[(size_t)MROWS*CDIM];
__device__ float g_K[(size_t)MROWS*KVDIM];
__device__ float g_V[(size_t)MROWS*KVDIM];
__device__ float g_cos[TSEQ*(HD/2)];
__device__ float g_sin[TSEQ*(HD/2)];

// bf16 hi/lo split buffers
__device__ __nv_bfloat16 g_xh[(size_t)MROWS*CDIM];
__device__ __nv_bfloat16 g_xl[(size_t)MROWS*CDIM];
__device__ __nv_bfloat16 g_Wqh[(size_t)CDIM*CDIM];
__device__ __nv_bfloat16 g_Wql[(size_t)CDIM*CDIM];
__device__ __nv_bfloat16 g_Wkh[(size_t)KVDIM*CDIM];
__device__ __nv_bfloat16 g_Wkl[(size_t)KVDIM*CDIM];
__device__ __nv_bfloat16 g_Wvh[(size_t)KVDIM*CDIM];
__device__ __nv_bfloat16 g_Wvl[(size_t)KVDIM*CDIM];
__device__ __nv_bfloat16 g_Woh[(size_t)CDIM*CDIM];
__device__ __nv_bfloat16 g_Wol[(size_t)CDIM*CDIM];
__device__ __nv_bfloat16 g_Ahh[(size_t)MROWS*CDIM];
__device__ __nv_bfloat16 g_All[(size_t)MROWS*CDIM];
// attention operand splits
__device__ __nv_bfloat16 g_Qbh[(size_t)MROWS*CDIM];
__device__ __nv_bfloat16 g_Qbl[(size_t)MROWS*CDIM];
__device__ __nv_bfloat16 g_Kbh[(size_t)MROWS*KVDIM];
__device__ __nv_bfloat16 g_Kbl[(size_t)MROWS*KVDIM];
__device__ __nv_bfloat16 g_Vbh[(size_t)MROWS*KVDIM];
__device__ __nv_bfloat16 g_Vbl[(size_t)MROWS*KVDIM];

// ---------------- small helpers ----------------
__device__ __forceinline__ uint32_t smem_u32(const void* p){
    uint32_t a;
    asm("{ .reg .u64 t; cvta.to.shared.u64 t, %1; cvt.u32.u64 %0, t; }" : "=r"(a) : "l"(p));
    return a;
}
__device__ __forceinline__ void cp16(uint32_t dst, const void* src){
    asm volatile("cp.async.cg.shared.global [%0], [%1], 16;" :: "r"(dst), "l"(src) : "memory");
}
#define CP_COMMIT() asm volatile("cp.async.commit_group;" ::: "memory")
#define CP_WAIT1()  asm volatile("cp.async.wait_group 1;" ::: "memory")

__device__ __forceinline__ void mma_bf16(float* c, const uint32_t* a, uint32_t b0, uint32_t b1){
    asm volatile(
        "mma.sync.aligned.m16n8k16.row.col.f32.bf16.bf16.f32 "
        "{%0,%1,%2,%3}, {%4,%5,%6,%7}, {%8,%9}, {%0,%1,%2,%3};"
        : "+f"(c[0]), "+f"(c[1]), "+f"(c[2]), "+f"(c[3])
        : "r"(a[0]), "r"(a[1]), "r"(a[2]), "r"(a[3]), "r"(b0), "r"(b1));
}
__device__ __forceinline__ uint32_t ld2bf(const __nv_bfloat16* p){
    return *(const uint32_t*)p;
}
// split (f0,f1) into packed bf16x2 hi + residual lo  (f0 in low half)
__device__ __forceinline__ void split_pack2(float f0, float f1, uint32_t& hi, uint32_t& lo){
    __nv_bfloat16 h0 = __float2bfloat16(f0);
    __nv_bfloat16 h1 = __float2bfloat16(f1);
    __nv_bfloat16 r0 = __float2bfloat16(f0 - __bfloat162float(h0));
    __nv_bfloat16 r1 = __float2bfloat16(f1 - __bfloat162float(h1));
    __nv_bfloat162 hh(h0, h1), ll(r0, r1);
    hi = *(uint32_t*)&hh;
    lo = *(uint32_t*)&ll;
}

// ---------------- RoPE trig table ----------------
__global__ void fill_trig_kernel() {
    int i = blockIdx.x * blockDim.x + threadIdx.x;
    if (i >= TSEQ * 64) return;
    int t = i >> 6;
    int f = i & 63;
    double theta = exp(((double)(-2 * f) / 128.0) * log(10000.0));
    double ang = (double)t * theta;
    const double twopi = 6.283185307179586476925286766559;
    double k = rint(ang / twopi);
    float rf = (float)(ang - k * twopi);
    g_cos[i] = cosf(rf);
    g_sin[i] = sinf(rf);
}

// ---------------- fp32 -> bf16 hi/lo split ----------------
__global__ __launch_bounds__(256) void split_kernel(
    const float* __restrict__ in, __nv_bfloat16* __restrict__ hi,
    __nv_bfloat16* __restrict__ lo, int n4)
{
    int i = blockIdx.x * blockDim.x + threadIdx.x;
    if (i >= n4) return;
    float4 v = ((const float4*)in)[i];
    uint32_t h0, l0, h1, l1;
    split_pack2(v.x, v.y, h0, l0);
    split_pack2(v.z, v.w, h1, l1);
    ((uint32_t*)hi)[2*i+0] = h0;
    ((uint32_t*)hi)[2*i+1] = h1;
    ((uint32_t*)lo)[2*i+0] = l0;
    ((uint32_t*)lo)[2*i+1] = l1;
}

// ------- bf16 split tensor-core GEMM: C[M,N] = A[M,K] * B[N,K]^T -----------
#define BPAD 40
#define TEL (128*BPAD)
#define STAGE_EL (4*TEL)
#define GEMM_SMEM_BYTES (2*STAGE_EL*2)

__global__ __launch_bounds__(256, 2) void bf16_gemm_kernel(
    const __nv_bfloat16* __restrict__ Ahp, const __nv_bfloat16* __restrict__ Alp,
    const __nv_bfloat16* __restrict__ Bhp, const __nv_bfloat16* __restrict__ Blp,
    float* __restrict__ C, int M, int N, int K)
{
    extern __shared__ __nv_bfloat16 smbf[];
    const int tid = threadIdx.x;
    const int wid = tid >> 5, lane = tid & 31;
    const int g = lane >> 2, t4 = lane & 3;
    const int wm = (wid >> 1) * 32;
    const int wn = (wid & 1) * 64;
    const int bm = blockIdx.y * 128, bn = blockIdx.x * 128;

    const uint32_t smb = smem_u32(smbf);
    float acc[2][8][4];
#pragma unroll
    for (int i = 0; i < 2; i++)
#pragma unroll
        for (int j = 0; j < 8; j++)
#pragma unroll
            for (int q = 0; q < 4; q++) acc[i][j][q] = 0.f;

    const int nch = K / 32;

    auto issue_chunk = [&](int c, int st) {
        const int k0 = c * 32;
        const uint32_t so = (uint32_t)st * (STAGE_EL * 2);
        const __nv_bfloat16* srcs[4] = {
            Ahp + (size_t)bm * K + k0, Alp + (size_t)bm * K + k0,
            Bhp + (size_t)bn * K + k0, Blp + (size_t)bn * K + k0 };
#pragma unroll
        for (int t = 0; t < 4; t++) {
#pragma unroll
            for (int p = 0; p < 2; p++) {
                int idx = tid + p * 256;
                int r = idx >> 2;
                int c8 = (idx & 3) * 8;
                cp16(smb + so + (uint32_t)(t * TEL + r * BPAD + c8) * 2u,
                     srcs[t] + (size_t)r * K + c8);
            }
        }
    };

    issue_chunk(0, 0); CP_COMMIT();
    issue_chunk(1, 1); CP_COMMIT();

    for (int c = 0; c < nch; c++) {
        CP_WAIT1();
        __syncthreads();
        const int st = c & 1;
        const __nv_bfloat16* Ahs = smbf + st * STAGE_EL;
        const __nv_bfloat16* Als = Ahs + TEL;
        const __nv_bfloat16* Bhs = Als + TEL;
        const __nv_bfloat16* Bls = Bhs + TEL;

#pragma unroll
        for (int kk = 0; kk < 32; kk += 16) {
            uint32_t ah[2][4], al[2][4];
#pragma unroll
            for (int mt = 0; mt < 2; mt++) {
                const __nv_bfloat16* ap = Ahs + (wm + mt * 16 + g) * BPAD + kk + 2 * t4;
                ah[mt][0] = ld2bf(ap);
                ah[mt][1] = ld2bf(ap + 8 * BPAD);
                ah[mt][2] = ld2bf(ap + 8);
                ah[mt][3] = ld2bf(ap + 8 * BPAD + 8);
                const __nv_bfloat16* aq = Als + (wm + mt * 16 + g) * BPAD + kk + 2 * t4;
                al[mt][0] = ld2bf(aq);
                al[mt][1] = ld2bf(aq + 8 * BPAD);
                al[mt][2] = ld2bf(aq + 8);
                al[mt][3] = ld2bf(aq + 8 * BPAD + 8);
            }
#pragma unroll
            for (int nt = 0; nt < 8; nt++) {
                const __nv_bfloat16* bp = Bhs + (wn + nt * 8 + g) * BPAD + kk + 2 * t4;
                uint32_t b0h = ld2bf(bp);
                uint32_t b1h = ld2bf(bp + 8);
                const __nv_bfloat16* bq = Bls + (wn + nt * 8 + g) * BPAD + kk + 2 * t4;
                uint32_t b0l = ld2bf(bq);
                uint32_t b1l = ld2bf(bq + 8);
                mma_bf16(acc[0][nt], ah[0], b0h, b1h);
                mma_bf16(acc[1][nt], ah[1], b0h, b1h);
                mma_bf16(acc[0][nt], ah[0], b0l, b1l);
                mma_bf16(acc[1][nt], ah[1], b0l, b1l);
                mma_bf16(acc[0][nt], al[0], b0h, b1h);
                mma_bf16(acc[1][nt], al[1], b0h, b1h);
            }
        }
        __syncthreads();
        if (c + 2 < nch) issue_chunk(c + 2, st);
        CP_COMMIT();
    }

#pragma unroll
    for (int mt = 0; mt < 2; mt++) {
        int r0 = bm + wm + mt * 16 + g;
#pragma unroll
        for (int nt = 0; nt < 8; nt++) {
            int col = bn + wn + nt * 8 + 2 * t4;
            float2 w0 = make_float2(acc[mt][nt][0], acc[mt][nt][1]);
            float2 w1 = make_float2(acc[mt][nt][2], acc[mt][nt][3]);
            *(float2*)(C + (size_t)r0 * N + col) = w0;
            *(float2*)(C + (size_t)(r0 + 8) * N + col) = w1;
        }
    }
}

// --------- RMSNorm + RoPE; emits bf16 hi/lo splits for attention -----------
__global__ __launch_bounds__(128) void norm_rope_kernel(const float* __restrict__ gain) {
    int row = blockIdx.x;
    const float* base;
    __nv_bfloat16 *dsth, *dstl;
    size_t off;
    int t, h;
    bool isQ = row < MROWS * NH;
    if (isQ) {
        int bt = row >> 4; h = row & 15;
        off = (size_t)bt * CDIM + h * HD;
        base = g_Q + off;
        dsth = g_Qbh + off; dstl = g_Qbl + off;
        t = bt & (TSEQ - 1);
    } else {
        int r2 = row - MROWS * NH;
        int bt = r2 >> 2; h = r2 & 3;
        off = (size_t)bt * KVDIM + h * HD;
        base = g_K + off;
        dsth = g_Kbh + off; dstl = g_Kbl + off;
        t = bt & (TSEQ - 1);
    }
    __shared__ float sh[128];
    __shared__ float red[4];
    int d = threadIdx.x;
    float v = base[d];
    float ss = v * v;
#pragma unroll
    for (int o = 16; o; o >>= 1) ss += __shfl_xor_sync(0xffffffffu, ss, o);
    if ((d & 31) == 0) red[d >> 5] = ss;
    __syncthreads();
    float tot = red[0] + red[1] + red[2] + red[3];
    float inv = rsqrtf(tot * (1.0f / 128.0f) + 1.1920928955078125e-07f);
    sh[d] = v * inv;
    __syncthreads();
    if (d < 64) {
        float te = sh[2 * d], to = sh[2 * d + 1];
        float c = g_cos[t * 64 + d];
        float s = g_sin[t * 64 + d];
        float re = te * c - to * s;
        float ro = te * s + to * c;
        float gm = isQ ? gain[h] * 0.08838834764831845f : 1.0f;
        uint32_t hi, lo;
        split_pack2(re * gm, ro * gm, hi, lo);
        ((uint32_t*)dsth)[d] = hi;
        ((uint32_t*)dstl)[d] = lo;
    }
}

// -------- Tensor-core flash attention (bf16 3-term split, causal, GQA) -----
// CTA: 64 q-rows, 4 warps x 16 q-rows. K-tile 64. Emits Ah/Al bf16 splits.
#define KPAD 136
#define VTPAD 70
#define ATT_Q_EL (64*KPAD)
#define ATT_VT_EL (128*VTPAD)
#define ATT_SMEM_BYTES ((4*ATT_Q_EL + 2*ATT_VT_EL)*2)   // 105472

__global__ __launch_bounds__(128, 2) void attn_tc_kernel() {
    extern __shared__ __nv_bfloat16 sma[];
    __nv_bfloat16* Qh  = sma;
    __nv_bfloat16* Ql  = Qh + ATT_Q_EL;
    __nv_bfloat16* Kh  = Ql + ATT_Q_EL;
    __nv_bfloat16* Kl  = Kh + ATT_Q_EL;
    __nv_bfloat16* Vth = Kl + ATT_Q_EL;
    __nv_bfloat16* Vtl = Vth + ATT_VT_EL;

    const int qt = blockIdx.x, h = blockIdx.y, b = blockIdx.z;
    const int kvh = h >> 2;
    const int tid = threadIdx.x, wid = tid >> 5, lane = tid & 31;
    const int g = lane >> 2, t4 = lane & 3;
    const int q0 = qt * 64, wq = wid * 16;

    const __nv_bfloat16* Qhb = g_Qbh + ((size_t)(b * TSEQ + q0)) * CDIM + h * HD;
    const __nv_bfloat16* Qlb = g_Qbl + ((size_t)(b * TSEQ + q0)) * CDIM + h * HD;
    const __nv_bfloat16* Khb = g_Kbh + ((size_t)b * TSEQ) * KVDIM + kvh * HD;
    const __nv_bfloat16* Klb = g_Kbl + ((size_t)b * TSEQ) * KVDIM + kvh * HD;
    const __nv_bfloat16* Vhb = g_Vbh + ((size_t)b * TSEQ) * KVDIM + kvh * HD;
    const __nv_bfloat16* Vlb = g_Vbl + ((size_t)b * TSEQ) * KVDIM + kvh * HD;

    // load Q tile (64 x 128, hi+lo)
    for (int f = tid; f < 1024; f += 128) {
        int r = f >> 4, c8 = (f & 15) * 8;
        *(uint4*)(Qh + r * KPAD + c8) = *(const uint4*)(Qhb + (size_t)r * CDIM + c8);
        *(uint4*)(Ql + r * KPAD + c8) = *(const uint4*)(Qlb + (size_t)r * CDIM + c8);
    }

    float o[16][4];
#pragma unroll
    for (int i = 0; i < 16; i++)
#pragma unroll
        for (int j = 0; j < 4; j++) o[i][j] = 0.f;
    float m0 = -1e30f, m1 = -1e30f, l0 = 0.f, l1 = 0.f;

    for (int kt = 0; kt <= qt; kt++) {
        const int k0 = kt * 64;
        __syncthreads();
        // load K tile [64 x 128] hi/lo
        for (int f = tid; f < 1024; f += 128) {
            int r = f >> 4, c8 = (f & 15) * 8;
            *(uint4*)(Kh + r * KPAD + c8) =
                *(const uint4*)(Khb + (size_t)(k0 + r) * KVDIM + c8);
            *(uint4*)(Kl + r * KPAD + c8) =
                *(const uint4*)(Klb + (size_t)(k0 + r) * KVDIM + c8);
        }
        // load V tile transposed -> Vt[d][token]
        for (int f = tid; f < 1024; f += 128) {
            int r = f >> 4, c8 = (f & 15) * 8;
            uint4 vh = *(const uint4*)(Vhb + (size_t)(k0 + r) * KVDIM + c8);
            uint4 vl = *(const uint4*)(Vlb + (size_t)(k0 + r) * KVDIM + c8);
            __nv_bfloat16 th[8], tl[8];
            *(uint4*)th = vh; *(uint4*)tl = vl;
#pragma unroll
            for (int j = 0; j < 8; j++) {
                Vth[(c8 + j) * VTPAD + r] = th[j];
                Vtl[(c8 + j) * VTPAD + r] = tl[j];
            }
        }
        __syncthreads();

        // ---- S = Q K^T (3-term split, fp32 accum) ----
        float s[8][4];
#pragma unroll
        for (int i = 0; i < 8; i++)
#pragma unroll
            for (int j = 0; j < 4; j++) s[i][j] = 0.f;

#pragma unroll
        for (int kk = 0; kk < 128; kk += 16) {
            uint32_t ah[4], al[4];
            const __nv_bfloat16* ap = Qh + (wq + g) * KPAD + kk + 2 * t4;
            ah[0] = ld2bf(ap);
            ah[1] = ld2bf(ap + 8 * KPAD);
            ah[2] = ld2bf(ap + 8);
            ah[3] = ld2bf(ap + 8 * KPAD + 8);
            const __nv_bfloat16* aq = Ql + (wq + g) * KPAD + kk + 2 * t4;
            al[0] = ld2bf(aq);
            al[1] = ld2bf(aq + 8 * KPAD);
            al[2] = ld2bf(aq + 8);
            al[3] = ld2bf(aq + 8 * KPAD + 8);
#pragma unroll
            for (int nt = 0; nt < 8; nt++) {
                const __nv_bfloat16* bp = Kh + (nt * 8 + g) * KPAD + kk + 2 * t4;
                uint32_t b0h = ld2bf(bp), b1h = ld2bf(bp + 8);
                const __nv_bfloat16* bq = Kl + (nt * 8 + g) * KPAD + kk + 2 * t4;
                uint32_t b0l = ld2bf(bq), b1l = ld2bf(bq + 8);
                mma_bf16(s[nt], ah, b0h, b1h);
                mma_bf16(s[nt], ah, b0l, b1l);
                mma_bf16(s[nt], al, b0h, b1h);
            }
        }

        // ---- causal mask on diagonal tile ----
        if (kt == qt) {
            int qr0 = q0 + wq + g, qr1 = qr0 + 8;
#pragma unroll
            for (int nt = 0; nt < 8; nt++) {
                int kc = k0 + nt * 8 + 2 * t4;
                if (kc     > qr0) s[nt][0] = -1e30f;
                if (kc + 1 > qr0) s[nt][1] = -1e30f;
                if (kc     > qr1) s[nt][2] = -1e30f;
                if (kc + 1 > qr1) s[nt][3] = -1e30f;
            }
        }

        // ---- online softmax (rows g and g+8) ----
        float mx0 = -1e30f, mx1 = -1e30f;
#pragma unroll
        for (int nt = 0; nt < 8; nt++) {
            mx0 = fmaxf(mx0, fmaxf(s[nt][0], s[nt][1]));
            mx1 = fmaxf(mx1, fmaxf(s[nt][2], s[nt][3]));
        }
        mx0 = fmaxf(mx0, __shfl_xor_sync(0xffffffffu, mx0, 1));
        mx0 = fmaxf(mx0, __shfl_xor_sync(0xffffffffu, mx0, 2));
        mx1 = fmaxf(mx1, __shfl_xor_sync(0xffffffffu, mx1, 1));
        mx1 = fmaxf(mx1, __shfl_xor_sync(0xffffffffu, mx1, 2));
        float mn0 = fmaxf(m0, mx0), mn1 = fmaxf(m1, mx1);
        float cr0 = __expf(m0 - mn0), cr1 = __expf(m1 - mn1);
        float sum0 = 0.f, sum1 = 0.f;
#pragma unroll
        for (int nt = 0; nt < 8; nt++) {
            s[nt][0] = __expf(s[nt][0] - mn0);
            s[nt][1] = __expf(s[nt][1] - mn0);
            s[nt][2] = __expf(s[nt][2] - mn1);
            s[nt][3] = __expf(s[nt][3] - mn1);
            sum0 += s[nt][0] + s[nt][1];
            sum1 += s[nt][2] + s[nt][3];
        }
        sum0 += __shfl_xor_sync(0xffffffffu, sum0, 1);
        sum0 += __shfl_xor_sync(0xffffffffu, sum0, 2);
        sum1 += __shfl_xor_sync(0xffffffffu, sum1, 1);
        sum1 += __shfl_xor_sync(0xffffffffu, sum1, 2);
        l0 = l0 * cr0 + sum0; m0 = mn0;
        l1 = l1 * cr1 + sum1; m1 = mn1;
#pragma unroll
        for (int nt = 0; nt < 16; nt++) {
            o[nt][0] *= cr0; o[nt][1] *= cr0;
            o[nt][2] *= cr1; o[nt][3] *= cr1;
        }

        // ---- O += P V (3-term split; P fragments from S registers) ----
#pragma unroll
        for (int jp = 0; jp < 4; jp++) {
            uint32_t pah[4], pal[4];
            split_pack2(s[2*jp  ][0], s[2*jp  ][1], pah[0], pal[0]);
            split_pack2(s[2*jp  ][2], s[2*jp  ][3], pah[1], pal[1]);
            split_pack2(s[2*jp+1][0], s[2*jp+1][1], pah[2], pal[2]);
            split_pack2(s[2*jp+1][2], s[2*jp+1][3], pah[3], pal[3]);
#pragma unroll
            for (int nt = 0; nt < 16; nt++) {
                const __nv_bfloat16* vp = Vth + (nt * 8 + g) * VTPAD + jp * 16 + 2 * t4;
                uint32_t b0h = ld2bf(vp), b1h = ld2bf(vp + 8);
                const __nv_bfloat16* vq = Vtl + (nt * 8 + g) * VTPAD + jp * 16 + 2 * t4;
                uint32_t b0l = ld2bf(vq), b1l = ld2bf(vq + 8);
                mma_bf16(o[nt], pah, b0h, b1h);
                mma_bf16(o[nt], pah, b0l, b1l);
                mma_bf16(o[nt], pal, b0h, b1h);
            }
        }
    }

    // ---- epilogue: normalize, split to bf16 hi/lo, store ----
    float inv0 = 1.0f / l0, inv1 = 1.0f / l1;
    size_t row0 = (size_t)(b * TSEQ + q0 + wq + g) * CDIM + h * HD;
    size_t row1 = row0 + (size_t)8 * CDIM;
#pragma unroll
    for (int nt = 0; nt < 16; nt++) {
        int col = nt * 8 + 2 * t4;
        uint32_t hi, lo;
        split_pack2(o[nt][0] * inv0, o[nt][1] * inv0, hi, lo);
        *(uint32_t*)(g_Ahh + row0 + col) = hi;
        *(uint32_t*)(g_All + row0 + col) = lo;
        split_pack2(o[nt][2] * inv1, o[nt][3] * inv1, hi, lo);
        *(uint32_t*)(g_Ahh + row1 + col) = hi;
        *(uint32_t*)(g_All + row1 + col) = lo;
    }
}

// ---------------- launch ----------------
extern "C" void kernel_launch(void* const* d_in, const int* in_sizes, int n_in,
                              void* d_out, int out_size) {
    const float* x    = (const float*)d_in[0];
    const float* Wq   = (const float*)d_in[1];
    const float* Wk   = (const float*)d_in[2];
    const float* Wv   = (const float*)d_in[3];
    const float* Wo   = (const float*)d_in[4];
    const float* gain = (const float*)d_in[5];
    float* out = (float*)d_out;

    float *pQ, *pK, *pV;
    cudaGetSymbolAddress((void**)&pQ, g_Q);
    cudaGetSymbolAddress((void**)&pK, g_K);
    cudaGetSymbolAddress((void**)&pV, g_V);
    __nv_bfloat16 *xh, *xl, *wqh, *wql, *wkh, *wkl, *wvh, *wvl, *woh, *wol, *ah, *al;
    __nv_bfloat16 *vbh, *vbl;
    cudaGetSymbolAddress((void**)&xh, g_xh);   cudaGetSymbolAddress((void**)&xl, g_xl);
    cudaGetSymbolAddress((void**)&wqh, g_Wqh); cudaGetSymbolAddress((void**)&wql, g_Wql);
    cudaGetSymbolAddress((void**)&wkh, g_Wkh); cudaGetSymbolAddress((void**)&wkl, g_Wkl);
    cudaGetSymbolAddress((void**)&wvh, g_Wvh); cudaGetSymbolAddress((void**)&wvl, g_Wvl);
    cudaGetSymbolAddress((void**)&woh, g_Woh); cudaGetSymbolAddress((void**)&wol, g_Wol);
    cudaGetSymbolAddress((void**)&ah, g_Ahh);  cudaGetSymbolAddress((void**)&al, g_All);
    cudaGetSymbolAddress((void**)&vbh, g_Vbh); cudaGetSymbolAddress((void**)&vbl, g_Vbl);

    cudaFuncSetAttribute(bf16_gemm_kernel, cudaFuncAttributeMaxDynamicSharedMemorySize,
                         GEMM_SMEM_BYTES);
    cudaFuncSetAttribute(attn_tc_kernel, cudaFuncAttributeMaxDynamicSharedMemorySize,
                         ATT_SMEM_BYTES);

    fill_trig_kernel<<<(TSEQ * 64 + 255) / 256, 256>>>();

    // splits of inputs
    split_kernel<<<(MROWS*CDIM/4 + 255)/256, 256>>>(x, xh, xl, MROWS*CDIM/4);
    split_kernel<<<(CDIM*CDIM/4 + 255)/256, 256>>>(Wq, wqh, wql, CDIM*CDIM/4);
    split_kernel<<<(KVDIM*CDIM/4 + 255)/256, 256>>>(Wk, wkh, wkl, KVDIM*CDIM/4);
    split_kernel<<<(KVDIM*CDIM/4 + 255)/256, 256>>>(Wv, wvh, wvl, KVDIM*CDIM/4);
    split_kernel<<<(CDIM*CDIM/4 + 255)/256, 256>>>(Wo, woh, wol, CDIM*CDIM/4);

    // projections
    dim3 gq(CDIM / 128, MROWS / 128);
    dim3 gkv(KVDIM / 128, MROWS / 128);
    bf16_gemm_kernel<<<gq,  256, GEMM_SMEM_BYTES>>>(xh, xl, wqh, wql, pQ, MROWS, CDIM, CDIM);
    bf16_gemm_kernel<<<gkv, 256, GEMM_SMEM_BYTES>>>(xh, xl, wkh, wkl, pK, MROWS, KVDIM, CDIM);
    bf16_gemm_kernel<<<gkv, 256, GEMM_SMEM_BYTES>>>(xh, xl, wvh, wvl, pV, MROWS, KVDIM, CDIM);

    // norm+rope -> Q/K bf16 splits;  V -> bf16 split
    norm_rope_kernel<<<MROWS * NH + MROWS * NKV, 128>>>(gain);
    split_kernel<<<(MROWS*KVDIM/4 + 255)/256, 256>>>(pV, vbh, vbl, MROWS*KVDIM/4);

    // tensor-core flash attention -> Ah/Al splits
    dim3 ga(TSEQ / 64, NH, BATCH);
    attn_tc_kernel<<<ga, 128, ATT_SMEM_BYTES>>>();

    // O projection
    bf16_gemm_kernel<<<gq, 256, GEMM_SMEM_BYTES>>>(ah, al, woh, wol, out, MROWS, CDIM, CDIM);
}